// round 4
// baseline (speedup 1.0000x reference)
#include <cuda_runtime.h>

// Problem constants (fixed by the reference)
#define B_     4
#define N_     4096
#define E_     128
#define CACHE_ 32
#define NK_    4
#define CE_    32      // channels per unit (E / NK)
#define M_     128     // N / CACHE
#define BNE_   (B_*N_*E_)
#define NW_    4       // warps per unit
#define CPW_   8       // channels per warp
#define KP_    4       // packed channel pairs per warp

// Inter-layer scratch (device globals: no allocation in kernel_launch)
__device__ float g_x [BNE_];
__device__ float g_xa[BNE_];

typedef unsigned long long u64;

__device__ __forceinline__ float tanh_fast(float x) {
    float y;
    asm("tanh.approx.f32 %0, %1;" : "=f"(y) : "f"(x));
    return y;
}
__device__ __forceinline__ u64 pk(float lo, float hi) {
    u64 r; asm("mov.b64 %0, {%1, %2};" : "=l"(r) : "f"(lo), "f"(hi)); return r;
}
__device__ __forceinline__ void upk(u64 x, float& lo, float& hi) {
    asm("mov.b64 {%0, %1}, %2;" : "=f"(lo), "=f"(hi) : "l"(x));
}
__device__ __forceinline__ u64 fma2(u64 a, u64 b, u64 c) {
    u64 d; asm("fma.rn.f32x2 %0, %1, %2, %3;" : "=l"(d) : "l"(a), "l"(b), "l"(c)); return d;
}
__device__ __forceinline__ u64 mul2(u64 a, u64 b) {
    u64 d; asm("mul.rn.f32x2 %0, %1, %2;" : "=l"(d) : "l"(a), "l"(b)); return d;
}
__device__ __forceinline__ u64 add2(u64 a, u64 b) {
    u64 d; asm("add.rn.f32x2 %0, %1, %2;" : "=l"(d) : "l"(a), "l"(b)); return d;
}

// 4 warps per (b,g,n) unit. lane = row-in-group. Warp w owns channels
// [w*8, w*8+8) as 4 packed f32 pairs. Rescaled state:
//   u2 = (xi/2)/0.9^j, v2 = (xa/2)/0.9^j  ->  v' = v + c_j*F; u' = u + 0.1*v'.
// Full running dots (true scale, replicated in all 4 warps, packed per lane):
//   X2 = (Ax=dot(xi,Wi), Bx=dot(xi,Wj)),  A2 = (Aa=dot(xa,Wi), Ba=dot(xa,Wj)).
// Per-step partial dot(F,W) summed across warps: double-buffered smem + 1 bar.
__global__ void __launch_bounds__(128, 12)
ncn_layer(const float* __restrict__ X, const float* __restrict__ XA,
          const float* __restrict__ W,         // 256 floats: Wi[4][32], Wj[4][32]
          float* __restrict__ YX, float* __restrict__ YA,
          int s)                                // group-index stride (0 or 1)
{
    __shared__ float  tile[CACHE_][CACHE_ + 1];
    __shared__ float2 ebuf[2][NW_][CACHE_];     // [parity][warp][lane]
    __shared__ float4 ibuf[NW_][CACHE_];        // init-dot exchange

    const int t    = threadIdx.x;
    const int w    = t >> 5;                    // warp in block (0..3)
    const int lane = t & 31;                    // row-in-group
    const int blk  = blockIdx.x;                // 0 .. 2047
    const int n    = blk & (NK_ - 1);
    const int g    = (blk >> 2) & (M_ - 1);
    const int b    = blk >> 9;

    const long long bBase    = (long long)b * N_ * E_;
    const long long chanBase = (long long)n * CE_ + lane;
    const int cw = w * CPW_;                    // this warp's first channel

    // ---- register-resident weights (uniform across lanes; L1-cached) ----
    u64 wI[KP_], wJ[KP_];
    #pragma unroll
    for (int k = 0; k < KP_; ++k) {
        int c = n * CE_ + cw + 2 * k;
        wI[k] = pk(__ldg(&W[c]),      __ldg(&W[c + 1]));
        wJ[k] = pk(__ldg(&W[E_ + c]), __ldg(&W[E_ + c + 1]));
    }

    u64 u2[KP_], v2[KP_];

    // ---- gather xi tile: warp w loads rows [w*8, w*8+8), coalesced ----
    #pragma unroll
    for (int r = 0; r < CPW_; ++r) {
        int rr  = cw + r;
        int row = ((g + rr * s) & (M_ - 1)) * CACHE_ + rr;
        tile[rr][lane] = X[bBase + (long long)row * E_ + chanBase];
    }
    __syncthreads();
    #pragma unroll
    for (int k = 0; k < KP_; ++k)
        u2[k] = pk(0.5f * tile[lane][cw + 2 * k], 0.5f * tile[lane][cw + 2 * k + 1]);
    __syncthreads();

    // ---- gather xa tile ----
    #pragma unroll
    for (int r = 0; r < CPW_; ++r) {
        int rr  = cw + r;
        int row = ((g + rr * s) & (M_ - 1)) * CACHE_ + rr;
        tile[rr][lane] = XA[bBase + (long long)row * E_ + chanBase];
    }
    __syncthreads();
    #pragma unroll
    for (int k = 0; k < KP_; ++k)
        v2[k] = pk(0.5f * tile[lane][cw + 2 * k], 0.5f * tile[lane][cw + 2 * k + 1]);

    const u64 K09 = pk(0.9f, 0.9f);
    const u64 K01 = pk(0.1f, 0.1f);
    const u64 Z   = pk(0.f, 0.f);

    // ---- initial partial dots (true scale = 2 * half-scale dot) ----
    {
        u64 ax = Z, bx = Z, aa = Z, ba = Z;
        #pragma unroll
        for (int k = 0; k < KP_; ++k) {
            ax = fma2(u2[k], wI[k], ax);
            bx = fma2(u2[k], wJ[k], bx);
            aa = fma2(v2[k], wI[k], aa);
            ba = fma2(v2[k], wJ[k], ba);
        }
        float l, h, Axp, Bxp, Aap, Bap;
        upk(ax, l, h); Axp = 2.f * (l + h);
        upk(bx, l, h); Bxp = 2.f * (l + h);
        upk(aa, l, h); Aap = 2.f * (l + h);
        upk(ba, l, h); Bap = 2.f * (l + h);
        ibuf[w][lane] = make_float4(Axp, Bxp, Aap, Bap);
    }
    __syncthreads();
    u64 X2, A2;  // (Ax,Bx), (Aa,Ba) — full totals, replicated in every warp
    {
        float4 p0 = ibuf[0][lane], p1 = ibuf[1][lane];
        float4 p2 = ibuf[2][lane], p3 = ibuf[3][lane];
        X2 = pk(p0.x + p1.x + p2.x + p3.x, p0.y + p1.y + p2.y + p3.y);
        A2 = pk(p0.z + p1.z + p2.z + p3.z, p0.w + p1.w + p2.w + p3.w);
    }

    float sc = 1.0f;                  // 0.9^j
    float cj = 0.05f / 0.9f;          // 0.05 / 0.9^(j+1)

    // ---- 32-step recurrence ----
    #pragma unroll 1
    for (int j = 0; j < CACHE_; ++j) {
        float Ax, Bx; upk(X2, Ax, Bx);
        float sim = Ax + __shfl_sync(0xffffffffu, Bx, j);
        u64 sim2 = pk(sim, sim);
        u64 s2   = pk(sc, sc);
        u64 c2   = pk(cj, cj);
        u64 SA = Z, SB = Z, DA = Z, DB = Z;
        #pragma unroll
        for (int k = 0; k < KP_; ++k) {
            u64 uj = __shfl_sync(0xffffffffu, u2[k], j);    // pre-update row j
            u64 T  = mul2(s2, fma2(sim2, uj, u2[k]));       // true-scale T
            float t0, t1; upk(T, t0, t1);
            u64 F = pk(tanh_fast(t0), tanh_fast(t1));
            if (k & 1) { SB = fma2(F, wI[k], SB); DB = fma2(F, wJ[k], DB); }
            else       { SA = fma2(F, wI[k], SA); DA = fma2(F, wJ[k], DA); }
            v2[k] = fma2(c2,  F,     v2[k]);                // ~xa update
            u2[k] = fma2(K01, v2[k], u2[k]);                // ~xi update
        }
        float l, h, SFp, DFp;
        { u64 q = add2(SA, SB); upk(q, l, h); SFp = l + h; }
        { u64 q = add2(DA, DB); upk(q, l, h); DFp = l + h; }

        int p = j & 1;
        ebuf[p][w][lane] = make_float2(SFp, DFp);
        __syncthreads();
        float2 q0 = ebuf[p][0][lane], q1 = ebuf[p][1][lane];
        float2 q2 = ebuf[p][2][lane], q3 = ebuf[p][3][lane];
        u64 S2 = pk((q0.x + q1.x) + (q2.x + q3.x),
                    (q0.y + q1.y) + (q2.y + q3.y));         // (SF, DF)

        A2 = fma2(A2, K09, mul2(S2, K01));                  // Aa,Ba update
        X2 = fma2(X2, K09, mul2(A2, K01));                  // Ax,Bx update
        sc *= 0.9f;
        cj *= (1.0f / 0.9f);
    }

    const float fscale = 2.0f * sc;   // undo half-scale and 0.9^32 rescale

    // ---- scatter yi ----
    __syncthreads();
    #pragma unroll
    for (int k = 0; k < KP_; ++k) {
        float l, h; upk(u2[k], l, h);
        tile[lane][cw + 2 * k]     = fscale * l;
        tile[lane][cw + 2 * k + 1] = fscale * h;
    }
    __syncthreads();
    #pragma unroll
    for (int r = 0; r < CPW_; ++r) {
        int rr  = cw + r;
        int row = ((g + rr * s) & (M_ - 1)) * CACHE_ + rr;
        YX[bBase + (long long)row * E_ + chanBase] = tile[rr][lane];
    }
    __syncthreads();

    // ---- scatter ya ----
    #pragma unroll
    for (int k = 0; k < KP_; ++k) {
        float l, h; upk(v2[k], l, h);
        tile[lane][cw + 2 * k]     = fscale * l;
        tile[lane][cw + 2 * k + 1] = fscale * h;
    }
    __syncthreads();
    #pragma unroll
    for (int r = 0; r < CPW_; ++r) {
        int rr  = cw + r;
        int row = ((g + rr * s) & (M_ - 1)) * CACHE_ + rr;
        YA[bBase + (long long)row * E_ + chanBase] = tile[rr][lane];
    }
}

extern "C" void kernel_launch(void* const* d_in, const int* in_sizes, int n_in,
                              void* d_out, int out_size) {
    const float* x  = (const float*)d_in[0];
    const float* xa = (const float*)d_in[1];
    const float* W  = (const float*)d_in[2];
    float* out = (float*)d_out;

    float *gx = nullptr, *gxa = nullptr;
    cudaGetSymbolAddress((void**)&gx,  g_x);
    cudaGetSymbolAddress((void**)&gxa, g_xa);

    dim3 grid(B_ * M_ * NK_);   // 2048 blocks
    dim3 block(128);            // 4 warps per unit

    // Layer 0: stage shift s = 0 (contiguous groups)
    ncn_layer<<<grid, block>>>(x, xa, W, gx, gxa, 0);
    // Layer 1: stage shift s = 1 (block = (g + o) % m), writes final output
    ncn_layer<<<grid, block>>>(gx, gxa, W + 2 * E_, out, out + BNE_, 1);
}

// round 5
// speedup vs baseline: 1.6714x; 1.6714x over previous
#include <cuda_runtime.h>

// Problem constants (fixed by the reference)
#define B_     4
#define N_     4096
#define E_     128
#define CACHE_ 32
#define NK_    4
#define CE_    32      // channels per unit (E / NK)
#define M_     128     // N / CACHE
#define BNE_   (B_*N_*E_)
#define NW_    2       // warps per unit
#define CPW_   16      // channels per warp
#define KP_    8       // packed channel pairs per warp

// Inter-layer scratch (device globals: no allocation in kernel_launch)
__device__ float g_x [BNE_];
__device__ float g_xa[BNE_];

typedef unsigned long long u64;

__device__ __forceinline__ float tanh_fast(float x) {
    float y;
    asm("tanh.approx.f32 %0, %1;" : "=f"(y) : "f"(x));
    return y;
}
__device__ __forceinline__ u64 pk(float lo, float hi) {
    u64 r; asm("mov.b64 %0, {%1, %2};" : "=l"(r) : "f"(lo), "f"(hi)); return r;
}
__device__ __forceinline__ void upk(u64 x, float& lo, float& hi) {
    asm("mov.b64 {%0, %1}, %2;" : "=f"(lo), "=f"(hi) : "l"(x));
}
__device__ __forceinline__ u64 fma2(u64 a, u64 b, u64 c) {
    u64 d; asm("fma.rn.f32x2 %0, %1, %2, %3;" : "=l"(d) : "l"(a), "l"(b), "l"(c)); return d;
}
__device__ __forceinline__ u64 mul2(u64 a, u64 b) {
    u64 d; asm("mul.rn.f32x2 %0, %1, %2;" : "=l"(d) : "l"(a), "l"(b)); return d;
}
__device__ __forceinline__ u64 add2(u64 a, u64 b) {
    u64 d; asm("add.rn.f32x2 %0, %1, %2;" : "=l"(d) : "l"(a), "l"(b)); return d;
}

// 2 warps per (b,g,n) unit. lane = row-in-group. Warp w owns channels
// [w*16, w*16+16) as 8 packed f32 pairs (state in regs, weights in smem).
// Rescaled state: u2=(xi/2)/0.9^j, v2=(xa/2)/0.9^j.
// LINEAR PARTIAL running dots (true scale, per warp over its channels):
//   X2w=(Ax_w,Bx_w), A2w=(Aa_w,Ba_w);  totals = sum over the 2 warps.
// Each warp updates its partials with its own SF_w/DF_w (valid by linearity).
// Per-step cross-warp traffic: one packed float2 (X2w) through a
// double-buffered smem slot + ONE __syncthreads.
__global__ void __launch_bounds__(64, 14)
ncn_layer(const float* __restrict__ X, const float* __restrict__ XA,
          const float* __restrict__ W,         // 256 floats: Wi[4][32], Wj[4][32]
          float* __restrict__ YX, float* __restrict__ YA,
          int s)                                // group-index stride (0 or 1)
{
    __shared__ float  tile[CACHE_][CACHE_ + 1];
    __shared__ float2 ebuf[2][NW_][CACHE_];     // [parity][warp][lane] = (Ax_w,Bx_w)
    __shared__ u64 sWi[CPW_ * NW_ / 2], sWj[CPW_ * NW_ / 2];  // 16 pairs = 32 ch

    const int t    = threadIdx.x;
    const int w    = t >> 5;                    // warp in block (0/1)
    const int lane = t & 31;                    // row-in-group
    const int blk  = blockIdx.x;                // 0 .. 2047
    const int n    = blk & (NK_ - 1);
    const int g    = (blk >> 2) & (M_ - 1);
    const int b    = blk >> 9;

    if (t < 16) {
        sWi[t] = pk(W[       n * CE_ + 2 * t], W[       n * CE_ + 2 * t + 1]);
        sWj[t] = pk(W[E_ +   n * CE_ + 2 * t], W[E_ +   n * CE_ + 2 * t + 1]);
    }

    const long long bBase    = (long long)b * N_ * E_;
    const long long chanBase = (long long)n * CE_ + lane;
    const int cw = w * CPW_;                    // this warp's first channel
    const int kw = w * KP_;                     // this warp's first weight pair

    u64 u2[KP_], v2[KP_];

    // ---- gather xi tile: warp w loads rows [w*16, w*16+16), coalesced ----
    #pragma unroll
    for (int r = 0; r < CPW_; ++r) {
        int rr  = cw + r;
        int row = ((g + rr * s) & (M_ - 1)) * CACHE_ + rr;
        tile[rr][lane] = X[bBase + (long long)row * E_ + chanBase];
    }
    __syncthreads();
    #pragma unroll
    for (int k = 0; k < KP_; ++k)
        u2[k] = pk(0.5f * tile[lane][cw + 2 * k], 0.5f * tile[lane][cw + 2 * k + 1]);
    __syncthreads();

    // ---- gather xa tile ----
    #pragma unroll
    for (int r = 0; r < CPW_; ++r) {
        int rr  = cw + r;
        int row = ((g + rr * s) & (M_ - 1)) * CACHE_ + rr;
        tile[rr][lane] = XA[bBase + (long long)row * E_ + chanBase];
    }
    __syncthreads();
    #pragma unroll
    for (int k = 0; k < KP_; ++k)
        v2[k] = pk(0.5f * tile[lane][cw + 2 * k], 0.5f * tile[lane][cw + 2 * k + 1]);

    const u64 K09 = pk(0.9f, 0.9f);
    const u64 K01 = pk(0.1f, 0.1f);
    const u64 Z   = pk(0.f, 0.f);

    // ---- initial partial dots (true scale = 2 * half-scale dot) ----
    u64 X2w, A2w;   // packed partials: (Ax_w,Bx_w), (Aa_w,Ba_w)
    {
        u64 ax = Z, bx = Z, aa = Z, ba = Z;
        #pragma unroll
        for (int k = 0; k < KP_; ++k) {
            u64 wi = sWi[kw + k], wj = sWj[kw + k];
            ax = fma2(u2[k], wi, ax);
            bx = fma2(u2[k], wj, bx);
            aa = fma2(v2[k], wi, aa);
            ba = fma2(v2[k], wj, ba);
        }
        float l, h, Axw, Bxw, Aaw, Baw;
        upk(ax, l, h); Axw = 2.f * (l + h);
        upk(bx, l, h); Bxw = 2.f * (l + h);
        upk(aa, l, h); Aaw = 2.f * (l + h);
        upk(ba, l, h); Baw = 2.f * (l + h);
        X2w = pk(Axw, Bxw);
        A2w = pk(Aaw, Baw);
        ebuf[0][w][lane] = make_float2(Axw, Bxw);   // publish for step 0
    }
    __syncthreads();

    float sc = 1.0f;                  // 0.9^j
    float cj = 0.05f / 0.9f;          // 0.05 / 0.9^(j+1)

    // ---- 32-step recurrence ----
    #pragma unroll 1
    for (int j = 0; j < CACHE_; ++j) {
        const int p = j & 1;

        // broadcast row j's state (independent of this step's exchange)
        u64 ujA[KP_];
        #pragma unroll
        for (int k = 0; k < KP_; ++k)
            ujA[k] = __shfl_sync(0xffffffffu, u2[k], j);

        // sim = (Ax_w,own + Ax_w,other)[lane] + (Bx_w0 + Bx_w1)[j]
        float2 other = ebuf[p][1 - w][lane];        // per-lane
        float2 bj0   = ebuf[p][0][j];               // broadcast LDS
        float2 bj1   = ebuf[p][1][j];               // broadcast LDS
        float Axw, Bxw_dummy; upk(X2w, Axw, Bxw_dummy);
        float sim = (Axw + other.x) + (bj0.y + bj1.y);

        u64 sim2 = pk(sim, sim);
        u64 s2   = pk(sc, sc);
        u64 c2   = pk(cj, cj);
        u64 SA = Z, SB = Z, DA = Z, DB = Z;
        #pragma unroll
        for (int k = 0; k < KP_; ++k) {
            u64 T = mul2(s2, fma2(sim2, ujA[k], u2[k]));    // true-scale T
            float t0, t1; upk(T, t0, t1);
            u64 F = pk(tanh_fast(t0), tanh_fast(t1));
            u64 wi = sWi[kw + k], wj = sWj[kw + k];
            if (k & 1) { SB = fma2(F, wi, SB); DB = fma2(F, wj, DB); }
            else       { SA = fma2(F, wi, SA); DA = fma2(F, wj, DA); }
            v2[k] = fma2(c2,  F,     v2[k]);                // ~xa update
            u2[k] = fma2(K01, v2[k], u2[k]);                // ~xi update
        }
        float l, h, SFw, DFw;
        { u64 q = add2(SA, SB); upk(q, l, h); SFw = l + h; }
        { u64 q = add2(DA, DB); upk(q, l, h); DFw = l + h; }

        // update OWN partials only (linearity) and publish for next step
        A2w = fma2(A2w, K09, mul2(pk(SFw, DFw), K01));      // (Aa_w,Ba_w)
        X2w = fma2(X2w, K09, mul2(A2w, K01));               // (Ax_w,Bx_w)
        float nAx, nBx; upk(X2w, nAx, nBx);
        ebuf[p ^ 1][w][lane] = make_float2(nAx, nBx);
        __syncthreads();                                    // one bar per step

        sc *= 0.9f;
        cj *= (1.0f / 0.9f);
    }

    const float fscale = 2.0f * sc;   // undo half-scale and 0.9^32 rescale

    // ---- scatter yi ----
    #pragma unroll
    for (int k = 0; k < KP_; ++k) {
        float l, h; upk(u2[k], l, h);
        tile[lane][cw + 2 * k]     = fscale * l;
        tile[lane][cw + 2 * k + 1] = fscale * h;
    }
    __syncthreads();
    #pragma unroll
    for (int r = 0; r < CPW_; ++r) {
        int rr  = cw + r;
        int row = ((g + rr * s) & (M_ - 1)) * CACHE_ + rr;
        YX[bBase + (long long)row * E_ + chanBase] = tile[rr][lane];
    }
    __syncthreads();

    // ---- scatter ya ----
    #pragma unroll
    for (int k = 0; k < KP_; ++k) {
        float l, h; upk(v2[k], l, h);
        tile[lane][cw + 2 * k]     = fscale * l;
        tile[lane][cw + 2 * k + 1] = fscale * h;
    }
    __syncthreads();
    #pragma unroll
    for (int r = 0; r < CPW_; ++r) {
        int rr  = cw + r;
        int row = ((g + rr * s) & (M_ - 1)) * CACHE_ + rr;
        YA[bBase + (long long)row * E_ + chanBase] = tile[rr][lane];
    }
}

extern "C" void kernel_launch(void* const* d_in, const int* in_sizes, int n_in,
                              void* d_out, int out_size) {
    const float* x  = (const float*)d_in[0];
    const float* xa = (const float*)d_in[1];
    const float* W  = (const float*)d_in[2];
    float* out = (float*)d_out;

    float *gx = nullptr, *gxa = nullptr;
    cudaGetSymbolAddress((void**)&gx,  g_x);
    cudaGetSymbolAddress((void**)&gxa, g_xa);

    dim3 grid(B_ * M_ * NK_);   // 2048 blocks
    dim3 block(64);             // 2 warps per unit

    // Layer 0: stage shift s = 0 (contiguous groups)
    ncn_layer<<<grid, block>>>(x, xa, W, gx, gxa, 0);
    // Layer 1: stage shift s = 1 (block = (g + o) % m), writes final output
    ncn_layer<<<grid, block>>>(gx, gxa, W + 2 * E_, out, out + BNE_, 1);
}